// round 10
// baseline (speedup 1.0000x reference)
#include <cuda_runtime.h>
#include <cstdint>

// Problem constants (LangevinSDEContiformer: B=1024, S=512, H=64, D_IN=3)
#define BB   1024
#define SS   512
#define HH   64
#define DIN  3
#define SM1  511    // S-1 steps

__device__ float d_sigsc[SM1 * HH];
__device__ float d_hstep[SM1];
__device__ float d_times[SM1];

__global__ void sigma_kernel(const float* __restrict__ ts,
                             const float* __restrict__ Wd1, const float* __restrict__ bd1,
                             const float* __restrict__ Wd2, const float* __restrict__ bd2,
                             const float* __restrict__ minp, const float* __restrict__ maxp)
{
    __shared__ float hh[32];
    int s = blockIdx.x;
    int tid = threadIdx.x;
    float t = ts[(size_t)s * DIN];
    if (tid < 32) hh[tid] = fmaxf(t * Wd1[tid] + bd1[tid], 0.0f);
    __syncthreads();
    float acc = bd2[tid];
    #pragma unroll
    for (int i = 0; i < 32; i++) acc += hh[i] * Wd2[i * HH + tid];
    float sp = fmaxf(acc, 0.0f) + log1pf(expf(-fabsf(acc)));
    float mind = fabsf(minp[0]);
    float maxd = fabsf(maxp[0]);
    float sig = fminf(fmaxf(sp + mind, mind), maxd);
    float hs = ts[(size_t)(s + 1) * DIN] - t;
    d_sigsc[s * HH + tid] = sig * sqrtf(hs);
    if (tid == 0) { d_hstep[s] = hs; d_times[s] = t; }
}

// ---------------------------------------------------------------------------
// f32x2 / bf16x2 helpers
// ---------------------------------------------------------------------------
typedef unsigned long long u64;

__device__ __forceinline__ void fma2(u64& acc, u64 a, u64 b) {
    asm("fma.rn.f32x2 %0, %1, %2, %0;" : "+l"(acc) : "l"(a), "l"(b));
}
__device__ __forceinline__ float fold2(u64 p) {
    unsigned int lo, hi;
    asm("mov.b64 {%0, %1}, %2;" : "=r"(lo), "=r"(hi) : "l"(p));
    return __uint_as_float(lo) + __uint_as_float(hi);
}
// bf16x2 word (lo = k-even, hi = k-odd) -> f32x2 pair
__device__ __forceinline__ u64 bfup(unsigned int u) {
    u64 r;
    asm("mov.b64 %0, {%1, %2};" : "=l"(r) : "r"(u << 16), "r"(u & 0xffff0000u));
    return r;
}
// pack two f32 -> bf16x2 (lo in low half)
__device__ __forceinline__ unsigned int packbf(float lo, float hi) {
    unsigned int r;
    asm("cvt.rn.bf16x2.f32 %0, %1, %2;" : "=r"(r) : "f"(hi), "f"(lo));
    return r;
}
__device__ __forceinline__ float tanh_fast(float x) {
    float y;
    asm("tanh.approx.f32 %0, %1;" : "=f"(y) : "f"(x));
    return y;
}

// ---------------------------------------------------------------------------
// Shared layout (in 4-byte words).
// Per CTA: 8 batch rows, 8 warps; each phase sweeps each weight matrix
// through the crossbar EXACTLY ONCE (r=8 row-blocking, m=2 col-blocking).
//   128-col phases (1,3): warp w -> jh = w&1 (64-col half), p = w>>1 (S=4 split)
//    64-col phases (2,4): warp w -> p = w (S=8 split)
// ---------------------------------------------------------------------------
#define OFF_WB1   0                      // [32][128] u32 bf16x2 pairs along k (W1 fwd)
#define OFF_WB2   (OFF_WB1 + 4096)       // [64][64]  u32 pairs along k (W2 fwd)
#define OFF_WB2T  (OFF_WB2 + 4096)       // [32][128] u32 pairs along j (W2^T bwd)
#define OFF_WB1T  (OFF_WB2T + 4096)      // [64][64]  u32 pairs along i (W1^T bwd)
#define OFF_W1T   (OFF_WB1T + 4096)      // [128] f32 t-row of W1
#define OFF_B1    (OFF_W1T + 128)        // [128]
#define OFF_B2    (OFF_B1 + 128)         // [64]
#define OFF_W3    (OFF_B2 + 64)          // [64]
#define OFF_Y     (OFF_W3 + 64)          // [8][64] f32
#define OFF_H1    (OFF_Y + 512)          // [8][128] f32
#define OFF_G2    (OFF_H1 + 1024)        // [8][64] f32
#define OFF_G1    (OFF_G2 + 512)         // [8][128] f32
#define OFF_PART  (OFF_G1 + 1024)        // 4096 f32 (S*8rows*C words, max 4096)
#define SMEM_WORDS (OFF_PART + 4096)     // 23936
#define SMEM_BYTES (SMEM_WORDS * 4)      // 95744

__global__ void __launch_bounds__(256, 1)
sde_scan_kernel(const float* __restrict__ ts, const float* __restrict__ noise,
                const float* __restrict__ Wp1, const float* __restrict__ bp1,
                const float* __restrict__ Wp2, const float* __restrict__ bp2,
                const float* __restrict__ Wp3, float* __restrict__ out)
{
    extern __shared__ unsigned int smu[];
    unsigned int* Wb1  = smu + OFF_WB1;
    unsigned int* Wb2  = smu + OFF_WB2;
    unsigned int* Wb2t = smu + OFF_WB2T;
    unsigned int* Wb1t = smu + OFF_WB1T;
    float* W1t = (float*)(smu + OFF_W1T);
    float* B1s = (float*)(smu + OFF_B1);
    float* B2s = (float*)(smu + OFF_B2);
    float* W3s = (float*)(smu + OFF_W3);
    float* Y   = (float*)(smu + OFF_Y);
    float* H1s = (float*)(smu + OFF_H1);
    float* G2s = (float*)(smu + OFF_G2);
    float* G1s = (float*)(smu + OFF_G1);
    float* PART= (float*)(smu + OFF_PART);

    const int tid  = threadIdx.x;
    const int lane = tid & 31;
    const int w    = tid >> 5;          // warp 0..7
    const int jh   = w & 1;             // 64-col half for 128-col phases
    const int p4   = w >> 1;            // split parity 0..3 (S=4 phases)
    const int p8   = w;                 // split parity 0..7 (S=8 phases)
    const int jcol = jh * 64 + lane;    // column in 128-col phases
    const int rowTop = blockIdx.x * 8;  // 8 rows per CTA

    // ---- pack weights into shared (bf16x2 pairs; 4 layouts)
    for (int i = tid; i < 4096; i += 256) {           // Wb1[k2][j]
        int k2 = i >> 7, j = i & 127;
        Wb1[i] = packbf(Wp1[(2 * k2) * 128 + j], Wp1[(2 * k2 + 1) * 128 + j]);
    }
    for (int i = tid; i < 4096; i += 256) {           // Wb2[k2][j]
        int k2 = i >> 6, j = i & 63;
        Wb2[i] = packbf(Wp2[(2 * k2) * 64 + j], Wp2[(2 * k2 + 1) * 64 + j]);
    }
    for (int i = tid; i < 4096; i += 256) {           // Wb2t[j2][i] (pairs along j)
        int j2 = i >> 7, ii = i & 127;
        Wb2t[i] = packbf(Wp2[ii * 64 + 2 * j2], Wp2[ii * 64 + 2 * j2 + 1]);
    }
    for (int i = tid; i < 4096; i += 256) {           // Wb1t[i2][kout] (pairs along i)
        int i2 = i >> 6, ko = i & 63;
        Wb1t[i] = packbf(Wp1[ko * 128 + 2 * i2], Wp1[ko * 128 + 2 * i2 + 1]);
    }
    if (tid < 128) { W1t[tid] = Wp1[64 * 128 + tid]; B1s[tid] = bp1[tid]; }
    if (tid < 64)  { B2s[tid] = bp2[tid]; W3s[tid] = Wp3[tid]; }

    // ---- init y0 (8x64 = 512 elems, 2 per thread) and write out[:,0,:]
    #pragma unroll
    for (int q = 0; q < 2; q++) {
        int e = q * 256 + tid;
        int k = e & 63, r = e >> 6;
        int b = rowTop + r;
        float v = (k < DIN) ? ts[(size_t)b * SS * DIN + k] : 0.0f;
        Y[r * 64 + k] = v;
        out[((size_t)b * SS) * HH + k] = v;
    }
    __syncthreads();

    for (int s = 0; s < SM1; s++) {
        const float tcur  = d_times[s];
        const float hstep = d_hstep[s];

        // prefetch noise*sigma for this thread's phase-4 outputs
        float zsc[2];
        #pragma unroll
        for (int q = 0; q < 2; q++) {
            int e = q * 256 + tid;
            int k = e & 63, r = e >> 6;
            int b = rowTop + r;
            zsc[q] = d_sigsc[s * HH + k] * noise[((size_t)s * BB + b) * HH + k];
        }

        // ===== phase 1: [y,t] @ W1 -> 8 rows x 128 cols; S=4, m=2, r=8 ======
        {
            u64 acc[8][2];
            #pragma unroll
            for (int r = 0; r < 8; r++) { acc[r][0] = 0ull; acc[r][1] = 0ull; }
            #pragma unroll
            for (int c = 0; c < 4; c++) {
                const int k0 = p4 * 16 + c * 4;       // 4 k values = 2 pairs
                ulonglong2 av[8];
                #pragma unroll
                for (int r = 0; r < 8; r++)
                    av[r] = *(const ulonglong2*)&Y[r * 64 + k0];
                #pragma unroll
                for (int sub = 0; sub < 2; sub++) {
                    const int k2 = p4 * 8 + c * 2 + sub;
                    u64 wp0 = bfup(Wb1[k2 * 128 + jcol]);
                    u64 wp1 = bfup(Wb1[k2 * 128 + jcol + 32]);
                    #pragma unroll
                    for (int r = 0; r < 8; r++) {
                        u64 a = sub ? av[r].y : av[r].x;
                        fma2(acc[r][0], a, wp0);
                        fma2(acc[r][1], a, wp1);
                    }
                }
            }
            #pragma unroll
            for (int r = 0; r < 8; r++) {
                PART[(p4 * 8 + r) * 128 + jcol]      = fold2(acc[r][0]);
                PART[(p4 * 8 + r) * 128 + jcol + 32] = fold2(acc[r][1]);
            }
        }
        __syncthreads();
        // combine: h1 = tanh(sum4 + t*W1t + b1)   (1024 outs, 4 per thread)
        #pragma unroll
        for (int q = 0; q < 4; q++) {
            int e = q * 256 + tid;
            int j = e & 127, r = e >> 7;
            float sum = (PART[(0 * 8 + r) * 128 + j] + PART[(1 * 8 + r) * 128 + j])
                      + (PART[(2 * 8 + r) * 128 + j] + PART[(3 * 8 + r) * 128 + j]);
            H1s[r * 128 + j] = tanh_fast(sum + fmaf(tcur, W1t[j], B1s[j]));
        }
        __syncthreads();

        // ===== phase 2: h1 @ W2 -> 8 rows x 64 cols; S=8, m=2, r=8 ==========
        {
            u64 acc[8][2];
            #pragma unroll
            for (int r = 0; r < 8; r++) { acc[r][0] = 0ull; acc[r][1] = 0ull; }
            #pragma unroll
            for (int c = 0; c < 4; c++) {
                const int k0 = p8 * 16 + c * 4;
                ulonglong2 av[8];
                #pragma unroll
                for (int r = 0; r < 8; r++)
                    av[r] = *(const ulonglong2*)&H1s[r * 128 + k0];
                #pragma unroll
                for (int sub = 0; sub < 2; sub++) {
                    const int k2 = p8 * 8 + c * 2 + sub;
                    u64 wp0 = bfup(Wb2[k2 * 64 + lane]);
                    u64 wp1 = bfup(Wb2[k2 * 64 + lane + 32]);
                    #pragma unroll
                    for (int r = 0; r < 8; r++) {
                        u64 a = sub ? av[r].y : av[r].x;
                        fma2(acc[r][0], a, wp0);
                        fma2(acc[r][1], a, wp1);
                    }
                }
            }
            #pragma unroll
            for (int r = 0; r < 8; r++) {
                PART[(p8 * 8 + r) * 64 + lane]      = fold2(acc[r][0]);
                PART[(p8 * 8 + r) * 64 + lane + 32] = fold2(acc[r][1]);
            }
        }
        __syncthreads();
        // combine: g2 = W3*(1 - tanh(sum8 + b2)^2)   (512 outs, 2 per thread)
        #pragma unroll
        for (int q = 0; q < 2; q++) {
            int e = q * 256 + tid;
            int j = e & 63, r = e >> 6;
            float sum = 0.f;
            #pragma unroll
            for (int pp = 0; pp < 8; pp++)
                sum += PART[(pp * 8 + r) * 64 + j];
            float h2 = tanh_fast(sum + B2s[j]);
            G2s[r * 64 + j] = W3s[j] * (1.0f - h2 * h2);
        }
        __syncthreads();

        // ===== phase 3: g2 @ W2^T -> 8 rows x 128 cols; S=4, m=2, r=8 =======
        {
            u64 acc[8][2];
            #pragma unroll
            for (int r = 0; r < 8; r++) { acc[r][0] = 0ull; acc[r][1] = 0ull; }
            #pragma unroll
            for (int c = 0; c < 4; c++) {
                const int j0 = p4 * 16 + c * 4;
                ulonglong2 av[8];
                #pragma unroll
                for (int r = 0; r < 8; r++)
                    av[r] = *(const ulonglong2*)&G2s[r * 64 + j0];
                #pragma unroll
                for (int sub = 0; sub < 2; sub++) {
                    const int j2 = p4 * 8 + c * 2 + sub;
                    u64 wp0 = bfup(Wb2t[j2 * 128 + jcol]);
                    u64 wp1 = bfup(Wb2t[j2 * 128 + jcol + 32]);
                    #pragma unroll
                    for (int r = 0; r < 8; r++) {
                        u64 a = sub ? av[r].y : av[r].x;
                        fma2(acc[r][0], a, wp0);
                        fma2(acc[r][1], a, wp1);
                    }
                }
            }
            #pragma unroll
            for (int r = 0; r < 8; r++) {
                PART[(p4 * 8 + r) * 128 + jcol]      = fold2(acc[r][0]);
                PART[(p4 * 8 + r) * 128 + jcol + 32] = fold2(acc[r][1]);
            }
        }
        __syncthreads();
        // combine: g1 = sum4 * (1 - h1^2)   (1024 outs, 4 per thread)
        #pragma unroll
        for (int q = 0; q < 4; q++) {
            int e = q * 256 + tid;
            int i = e & 127, r = e >> 7;
            float sum = (PART[(0 * 8 + r) * 128 + i] + PART[(1 * 8 + r) * 128 + i])
                      + (PART[(2 * 8 + r) * 128 + i] + PART[(3 * 8 + r) * 128 + i]);
            float h1v = H1s[r * 128 + i];
            G1s[r * 128 + i] = sum * (1.0f - h1v * h1v);
        }
        __syncthreads();

        // ===== phase 4: g1 @ W1^T -> dy (8 rows x 64); S=8, m=2, r=8 ========
        {
            u64 acc[8][2];
            #pragma unroll
            for (int r = 0; r < 8; r++) { acc[r][0] = 0ull; acc[r][1] = 0ull; }
            #pragma unroll
            for (int c = 0; c < 4; c++) {
                const int i0 = p8 * 16 + c * 4;
                ulonglong2 av[8];
                #pragma unroll
                for (int r = 0; r < 8; r++)
                    av[r] = *(const ulonglong2*)&G1s[r * 128 + i0];
                #pragma unroll
                for (int sub = 0; sub < 2; sub++) {
                    const int i2 = p8 * 8 + c * 2 + sub;
                    u64 wp0 = bfup(Wb1t[i2 * 64 + lane]);
                    u64 wp1 = bfup(Wb1t[i2 * 64 + lane + 32]);
                    #pragma unroll
                    for (int r = 0; r < 8; r++) {
                        u64 a = sub ? av[r].y : av[r].x;
                        fma2(acc[r][0], a, wp0);
                        fma2(acc[r][1], a, wp1);
                    }
                }
            }
            #pragma unroll
            for (int r = 0; r < 8; r++) {
                PART[(p8 * 8 + r) * 64 + lane]      = fold2(acc[r][0]);
                PART[(p8 * 8 + r) * 64 + lane + 32] = fold2(acc[r][1]);
            }
        }
        __syncthreads();
        // combine: y += -dy*h + sig*z*sqrt(h); write out  (2 per thread)
        #pragma unroll
        for (int q = 0; q < 2; q++) {
            int e = q * 256 + tid;
            int k = e & 63, r = e >> 6;
            float dy = 0.f;
            #pragma unroll
            for (int pp = 0; pp < 8; pp++)
                dy += PART[(pp * 8 + r) * 64 + k];
            int b = rowTop + r;
            float ynew = fmaf(-dy, hstep, Y[r * 64 + k]) + zsc[q];
            Y[r * 64 + k] = ynew;
            out[((size_t)b * SS + (s + 1)) * HH + k] = ynew;
        }
        __syncthreads();
    }
}

// ---------------------------------------------------------------------------
extern "C" void kernel_launch(void* const* d_in, const int* in_sizes, int n_in,
                              void* d_out, int out_size)
{
    (void)in_sizes; (void)n_in; (void)out_size;
    const float* ts    = (const float*)d_in[0];   // time_series (B,S,3)
    const float* noise = (const float*)d_in[1];   // (S-1,B,H)
    const float* Wp1   = (const float*)d_in[2];   // (65,128)
    const float* bp1   = (const float*)d_in[3];   // (128,)
    const float* Wp2   = (const float*)d_in[4];   // (128,64)
    const float* bp2   = (const float*)d_in[5];   // (64,)
    const float* Wp3   = (const float*)d_in[6];   // (64,1)
    // d_in[7] = bp3 (unused: constant shift, zero gradient)
    const float* Wd1   = (const float*)d_in[8];   // (1,32)
    const float* bd1   = (const float*)d_in[9];   // (32,)
    const float* Wd2   = (const float*)d_in[10];  // (32,64)
    const float* bd2   = (const float*)d_in[11];  // (64,)
    const float* mn    = (const float*)d_in[12];  // scalar
    const float* mx    = (const float*)d_in[13];  // scalar
    float* out = (float*)d_out;

    cudaFuncSetAttribute(sde_scan_kernel,
                         cudaFuncAttributeMaxDynamicSharedMemorySize, SMEM_BYTES);

    sigma_kernel<<<SM1, HH>>>(ts, Wd1, bd1, Wd2, bd2, mn, mx);
    sde_scan_kernel<<<BB / 8, 256, SMEM_BYTES>>>(ts, noise, Wp1, bp1, Wp2, bp2, Wp3, out);
}

// round 11
// speedup vs baseline: 1.2329x; 1.2329x over previous
#include <cuda_runtime.h>
#include <cstdint>

// Problem constants (LangevinSDEContiformer: B=1024, S=512, H=64, D_IN=3)
#define BB   1024
#define SS   512
#define HH   64
#define DIN  3
#define SM1  511    // S-1 steps

__device__ float d_sigsc[SM1 * HH];
__device__ float d_hstep[SM1];
__device__ float d_times[SM1];

__global__ void sigma_kernel(const float* __restrict__ ts,
                             const float* __restrict__ Wd1, const float* __restrict__ bd1,
                             const float* __restrict__ Wd2, const float* __restrict__ bd2,
                             const float* __restrict__ minp, const float* __restrict__ maxp)
{
    __shared__ float hh[32];
    int s = blockIdx.x;
    int tid = threadIdx.x;
    float t = ts[(size_t)s * DIN];
    if (tid < 32) hh[tid] = fmaxf(t * Wd1[tid] + bd1[tid], 0.0f);
    __syncthreads();
    float acc = bd2[tid];
    #pragma unroll
    for (int i = 0; i < 32; i++) acc += hh[i] * Wd2[i * HH + tid];
    float sp = fmaxf(acc, 0.0f) + log1pf(expf(-fabsf(acc)));
    float mind = fabsf(minp[0]);
    float maxd = fabsf(maxp[0]);
    float sig = fminf(fmaxf(sp + mind, mind), maxd);
    float hs = ts[(size_t)(s + 1) * DIN] - t;
    d_sigsc[s * HH + tid] = sig * sqrtf(hs);
    if (tid == 0) { d_hstep[s] = hs; d_times[s] = t; }
}

// ---------------------------------------------------------------------------
// f32x2 / bf16x2 helpers
// ---------------------------------------------------------------------------
typedef unsigned long long u64;

__device__ __forceinline__ void fma2(u64& acc, u64 a, u64 b) {
    asm("fma.rn.f32x2 %0, %1, %2, %0;" : "+l"(acc) : "l"(a), "l"(b));
}
__device__ __forceinline__ float fold2(u64 p) {
    unsigned int lo, hi;
    asm("mov.b64 {%0, %1}, %2;" : "=r"(lo), "=r"(hi) : "l"(p));
    return __uint_as_float(lo) + __uint_as_float(hi);
}
__device__ __forceinline__ u64 bfup(unsigned int u) {
    u64 r;
    asm("mov.b64 %0, {%1, %2};" : "=l"(r) : "r"(u << 16), "r"(u & 0xffff0000u));
    return r;
}
__device__ __forceinline__ unsigned int packbf(float lo, float hi) {
    unsigned int r;
    asm("cvt.rn.bf16x2.f32 %0, %1, %2;" : "=r"(r) : "f"(hi), "f"(lo));
    return r;
}
__device__ __forceinline__ float tanh_fast(float x) {
    float y;
    asm("tanh.approx.f32 %0, %1;" : "=f"(y) : "f"(x));
    return y;
}

// ---------------------------------------------------------------------------
// Shared layout (4-byte words). 128 CTAs x 256 thr; 2 groups x (4 warps, 4 rows).
// k-split-4 per group; combine passes fused into consumer-warp prologues.
// PA: partials for 128-col phases (1,3):  [2 grp][4 par][4 row][128]  = 4096
// PB: partials for  64-col phases (2,4):  [2 grp][4 par][4 row][65]   = 2080+
// ---------------------------------------------------------------------------
#define PB_STRIDE 65
#define OFF_WB1   0                      // [32][128] u32 bf16x2 pairs along k (W1 fwd)
#define OFF_WB2   (OFF_WB1 + 4096)       // [64][64]  u32 pairs along k (W2 fwd)
#define OFF_WB2T  (OFF_WB2 + 4096)       // [32][128] u32 pairs along j (W2^T bwd)
#define OFF_WB1T  (OFF_WB2T + 4096)      // [64][64]  u32 pairs along i (W1^T bwd)
#define OFF_W1T   (OFF_WB1T + 4096)      // [128] f32 t-row of W1
#define OFF_B1    (OFF_W1T + 128)        // [128]
#define OFF_B2    (OFF_B1 + 128)         // [64]
#define OFF_W3    (OFF_B2 + 64)          // [64]
#define OFF_Y     (OFF_W3 + 64)          // [8][64] f32
#define OFF_H1    (OFF_Y + 512)          // [8][128] f32
#define OFF_G2    (OFF_H1 + 1024)        // [8][64] f32
#define OFF_G1    (OFF_G2 + 512)         // [8][128] f32
#define OFF_PA    (OFF_G1 + 1024)        // 4096 f32
#define OFF_PB    (OFF_PA + 4096)        // 32*65 = 2080 f32
#define SMEM_WORDS (OFF_PB + 2080 + 16)
#define SMEM_BYTES (SMEM_WORDS * 4)      // ~88 KB

__global__ void __launch_bounds__(256, 1)
sde_scan_kernel(const float* __restrict__ ts, const float* __restrict__ noise,
                const float* __restrict__ Wp1, const float* __restrict__ bp1,
                const float* __restrict__ Wp2, const float* __restrict__ bp2,
                const float* __restrict__ Wp3, float* __restrict__ out)
{
    extern __shared__ unsigned int smu[];
    unsigned int* Wb1  = smu + OFF_WB1;
    unsigned int* Wb2  = smu + OFF_WB2;
    unsigned int* Wb2t = smu + OFF_WB2T;
    unsigned int* Wb1t = smu + OFF_WB1T;
    float* W1t = (float*)(smu + OFF_W1T);
    float* B1s = (float*)(smu + OFF_B1);
    float* B2s = (float*)(smu + OFF_B2);
    float* W3s = (float*)(smu + OFF_W3);
    float* Y   = (float*)(smu + OFF_Y);
    float* H1s = (float*)(smu + OFF_H1);
    float* G2s = (float*)(smu + OFF_G2);
    float* G1s = (float*)(smu + OFF_G1);
    float* PA  = (float*)(smu + OFF_PA);
    float* PB  = (float*)(smu + OFF_PB);

    const int tid  = threadIdx.x;
    const int lane = tid & 31;
    const int wid  = tid >> 5;
    const int g    = wid >> 2;           // row group 0/1 (4 rows each)
    const int p    = wid & 3;            // split parity 0..3
    const int rbase = g * 4;
    const int rowTop = blockIdx.x * 8;
    const int barid = g + 1;             // per-group named barrier (128 thr)

    const int l16  = lane & 15;          // sub-lane for 16-wide chunks
    const int rA   = lane >> 4;          // row 0/1 (and +2) for 16-wide chunks

    // ---- pack weights into shared (bf16x2 pairs; 4 layouts)
    for (int i = tid; i < 4096; i += 256) {           // Wb1[k2][j]
        int k2 = i >> 7, j = i & 127;
        Wb1[i] = packbf(Wp1[(2 * k2) * 128 + j], Wp1[(2 * k2 + 1) * 128 + j]);
    }
    for (int i = tid; i < 4096; i += 256) {           // Wb2[k2][j]
        int k2 = i >> 6, j = i & 63;
        Wb2[i] = packbf(Wp2[(2 * k2) * 64 + j], Wp2[(2 * k2 + 1) * 64 + j]);
    }
    for (int i = tid; i < 4096; i += 256) {           // Wb2t[j2][i]
        int j2 = i >> 7, ii = i & 127;
        Wb2t[i] = packbf(Wp2[ii * 64 + 2 * j2], Wp2[ii * 64 + 2 * j2 + 1]);
    }
    for (int i = tid; i < 4096; i += 256) {           // Wb1t[i2][kout]
        int i2 = i >> 6, ko = i & 63;
        Wb1t[i] = packbf(Wp1[ko * 128 + 2 * i2], Wp1[ko * 128 + 2 * i2 + 1]);
    }
    if (tid < 128) { W1t[tid] = Wp1[64 * 128 + tid]; B1s[tid] = bp1[tid]; }
    if (tid < 64)  { B2s[tid] = bp2[tid]; W3s[tid] = Wp3[tid]; }

    // ---- init y0 and write out[:,0,:]
    #pragma unroll
    for (int q = 0; q < 2; q++) {
        int e = q * 256 + tid;
        int k = e & 63, r8 = e >> 6;
        int b = rowTop + r8;
        float v = (k < DIN) ? ts[(size_t)b * SS * DIN + k] : 0.0f;
        Y[r8 * 64 + k] = v;
        out[((size_t)b * SS) * HH + k] = v;
    }
    __syncthreads();

    for (int s = 0; s < SM1; s++) {
        const float tcur  = d_times[s];
        const float hstep = d_hstep[s];

        // prefetch noise*sigma for THIS warp's ynew chunk:
        //   k = p*16 + l16, rows rbase + rA and rbase + rA + 2
        const int kz = p * 16 + l16;
        float zsc[2];
        #pragma unroll
        for (int q = 0; q < 2; q++) {
            int r = rA + 2 * q;
            int b = rowTop + rbase + r;
            zsc[q] = d_sigsc[s * HH + kz] * noise[((size_t)s * BB + b) * HH + kz];
        }

        // ===== P1 matmul: [y,t] @ W1 partials; own k-chunk [p*16,p*16+16) ===
        {
            u64 acc[4][4];
            #pragma unroll
            for (int r = 0; r < 4; r++)
                #pragma unroll
                for (int m = 0; m < 4; m++) acc[r][m] = 0ull;
            #pragma unroll
            for (int n = 0; n < 8; n++) {
                const int k2 = p * 8 + n;             // k pair
                u64 av[4];
                #pragma unroll
                for (int r = 0; r < 4; r++)
                    av[r] = *(const u64*)&Y[(rbase + r) * 64 + 2 * k2];
                u64 wp[4];
                #pragma unroll
                for (int m = 0; m < 4; m++)
                    wp[m] = bfup(Wb1[k2 * 128 + lane + 32 * m]);
                #pragma unroll
                for (int r = 0; r < 4; r++)
                    #pragma unroll
                    for (int m = 0; m < 4; m++) fma2(acc[r][m], av[r], wp[m]);
            }
            #pragma unroll
            for (int r = 0; r < 4; r++)
                #pragma unroll
                for (int m = 0; m < 4; m++)
                    PA[((g * 4 + p) * 4 + r) * 128 + lane + 32 * m] = fold2(acc[r][m]);
        }
        asm volatile("bar.sync %0, %1;" :: "r"(barid), "r"(128) : "memory");

        // ===== P2 prologue (fused combine): h1 for own k-chunk [p*32,+32) ===
        {
            const int j = p * 32 + lane;
            #pragma unroll
            for (int r = 0; r < 4; r++) {
                float sum = (PA[((g * 4 + 0) * 4 + r) * 128 + j]
                           + PA[((g * 4 + 1) * 4 + r) * 128 + j])
                          + (PA[((g * 4 + 2) * 4 + r) * 128 + j]
                           + PA[((g * 4 + 3) * 4 + r) * 128 + j]);
                H1s[(rbase + r) * 128 + j] = tanh_fast(sum + fmaf(tcur, W1t[j], B1s[j]));
            }
        }
        __syncwarp();
        // ===== P2 matmul: h1 @ W2 partials; own k-chunk [p*32,+32) ==========
        {
            u64 acc[4][2];
            #pragma unroll
            for (int r = 0; r < 4; r++) { acc[r][0] = 0ull; acc[r][1] = 0ull; }
            #pragma unroll
            for (int n = 0; n < 16; n++) {
                const int k2 = p * 16 + n;
                u64 av[4];
                #pragma unroll
                for (int r = 0; r < 4; r++)
                    av[r] = *(const u64*)&H1s[(rbase + r) * 128 + 2 * k2];
                u64 wp[2];
                #pragma unroll
                for (int m = 0; m < 2; m++)
                    wp[m] = bfup(Wb2[k2 * 64 + lane + 32 * m]);
                #pragma unroll
                for (int r = 0; r < 4; r++)
                    #pragma unroll
                    for (int m = 0; m < 2; m++) fma2(acc[r][m], av[r], wp[m]);
            }
            #pragma unroll
            for (int r = 0; r < 4; r++)
                #pragma unroll
                for (int m = 0; m < 2; m++)
                    PB[((g * 4 + p) * 4 + r) * PB_STRIDE + lane + 32 * m] = fold2(acc[r][m]);
        }
        asm volatile("bar.sync %0, %1;" :: "r"(barid), "r"(128) : "memory");

        // ===== P3 prologue (fused combine): g2 for own j-chunk [p*16,+16) ===
        {
            const int j = p * 16 + l16;
            #pragma unroll
            for (int q = 0; q < 2; q++) {
                int r = rA + 2 * q;
                float sum = (PB[((g * 4 + 0) * 4 + r) * PB_STRIDE + j]
                           + PB[((g * 4 + 1) * 4 + r) * PB_STRIDE + j])
                          + (PB[((g * 4 + 2) * 4 + r) * PB_STRIDE + j]
                           + PB[((g * 4 + 3) * 4 + r) * PB_STRIDE + j]);
                float h2 = tanh_fast(sum + B2s[j]);
                G2s[(rbase + r) * 64 + j] = W3s[j] * (1.0f - h2 * h2);
            }
        }
        __syncwarp();
        // ===== P3 matmul: g2 @ W2^T partials; own j-chunk [p*16,+16) ========
        {
            u64 acc[4][4];
            #pragma unroll
            for (int r = 0; r < 4; r++)
                #pragma unroll
                for (int m = 0; m < 4; m++) acc[r][m] = 0ull;
            #pragma unroll
            for (int n = 0; n < 8; n++) {
                const int j2 = p * 8 + n;
                u64 av[4];
                #pragma unroll
                for (int r = 0; r < 4; r++)
                    av[r] = *(const u64*)&G2s[(rbase + r) * 64 + 2 * j2];
                u64 wp[4];
                #pragma unroll
                for (int m = 0; m < 4; m++)
                    wp[m] = bfup(Wb2t[j2 * 128 + lane + 32 * m]);
                #pragma unroll
                for (int r = 0; r < 4; r++)
                    #pragma unroll
                    for (int m = 0; m < 4; m++) fma2(acc[r][m], av[r], wp[m]);
            }
            #pragma unroll
            for (int r = 0; r < 4; r++)
                #pragma unroll
                for (int m = 0; m < 4; m++)
                    PA[((g * 4 + p) * 4 + r) * 128 + lane + 32 * m] = fold2(acc[r][m]);
        }
        asm volatile("bar.sync %0, %1;" :: "r"(barid), "r"(128) : "memory");

        // ===== P4 prologue (fused combine): g1 for own i-chunk [p*32,+32) ===
        {
            const int i = p * 32 + lane;
            #pragma unroll
            for (int r = 0; r < 4; r++) {
                float sum = (PA[((g * 4 + 0) * 4 + r) * 128 + i]
                           + PA[((g * 4 + 1) * 4 + r) * 128 + i])
                          + (PA[((g * 4 + 2) * 4 + r) * 128 + i]
                           + PA[((g * 4 + 3) * 4 + r) * 128 + i]);
                float h1v = H1s[(rbase + r) * 128 + i];
                G1s[(rbase + r) * 128 + i] = sum * (1.0f - h1v * h1v);
            }
        }
        __syncwarp();
        // ===== P4 matmul: g1 @ W1^T partials; own i-chunk [p*32,+32) ========
        {
            u64 acc[4][2];
            #pragma unroll
            for (int r = 0; r < 4; r++) { acc[r][0] = 0ull; acc[r][1] = 0ull; }
            #pragma unroll
            for (int n = 0; n < 16; n++) {
                const int i2 = p * 16 + n;
                u64 av[4];
                #pragma unroll
                for (int r = 0; r < 4; r++)
                    av[r] = *(const u64*)&G1s[(rbase + r) * 128 + 2 * i2];
                u64 wp[2];
                #pragma unroll
                for (int m = 0; m < 2; m++)
                    wp[m] = bfup(Wb1t[i2 * 64 + lane + 32 * m]);
                #pragma unroll
                for (int r = 0; r < 4; r++)
                    #pragma unroll
                    for (int m = 0; m < 2; m++) fma2(acc[r][m], av[r], wp[m]);
            }
            #pragma unroll
            for (int r = 0; r < 4; r++)
                #pragma unroll
                for (int m = 0; m < 2; m++)
                    PB[((g * 4 + p) * 4 + r) * PB_STRIDE + lane + 32 * m] = fold2(acc[r][m]);
        }
        asm volatile("bar.sync %0, %1;" :: "r"(barid), "r"(128) : "memory");

        // ===== step tail (fused combine): ynew for own k-chunk [p*16,+16) ===
        // next P1 reads only this warp's Y chunk -> __syncwarp suffices.
        {
            #pragma unroll
            for (int q = 0; q < 2; q++) {
                int r = rA + 2 * q;
                float dy = (PB[((g * 4 + 0) * 4 + r) * PB_STRIDE + kz]
                          + PB[((g * 4 + 1) * 4 + r) * PB_STRIDE + kz])
                         + (PB[((g * 4 + 2) * 4 + r) * PB_STRIDE + kz]
                          + PB[((g * 4 + 3) * 4 + r) * PB_STRIDE + kz]);
                int r8 = rbase + r;
                int b = rowTop + r8;
                float ynew = fmaf(-dy, hstep, Y[r8 * 64 + kz]) + zsc[q];
                Y[r8 * 64 + kz] = ynew;
                out[((size_t)b * SS + (s + 1)) * HH + kz] = ynew;
            }
        }
        __syncwarp();
    }
}

// ---------------------------------------------------------------------------
extern "C" void kernel_launch(void* const* d_in, const int* in_sizes, int n_in,
                              void* d_out, int out_size)
{
    (void)in_sizes; (void)n_in; (void)out_size;
    const float* ts    = (const float*)d_in[0];   // time_series (B,S,3)
    const float* noise = (const float*)d_in[1];   // (S-1,B,H)
    const float* Wp1   = (const float*)d_in[2];   // (65,128)
    const float* bp1   = (const float*)d_in[3];   // (128,)
    const float* Wp2   = (const float*)d_in[4];   // (128,64)
    const float* bp2   = (const float*)d_in[5];   // (64,)
    const float* Wp3   = (const float*)d_in[6];   // (64,1)
    // d_in[7] = bp3 (unused: constant shift, zero gradient)
    const float* Wd1   = (const float*)d_in[8];   // (1,32)
    const float* bd1   = (const float*)d_in[9];   // (32,)
    const float* Wd2   = (const float*)d_in[10];  // (32,64)
    const float* bd2   = (const float*)d_in[11];  // (64,)
    const float* mn    = (const float*)d_in[12];  // scalar
    const float* mx    = (const float*)d_in[13];  // scalar
    float* out = (float*)d_out;

    cudaFuncSetAttribute(sde_scan_kernel,
                         cudaFuncAttributeMaxDynamicSharedMemorySize, SMEM_BYTES);

    sigma_kernel<<<SM1, HH>>>(ts, Wd1, bd1, Wd2, bd2, mn, mx);
    sde_scan_kernel<<<BB / 8, 256, SMEM_BYTES>>>(ts, noise, Wp1, bp1, Wp2, bp2, Wp3, out);
}